// round 4
// baseline (speedup 1.0000x reference)
#include <cuda_runtime.h>

// ---------------------------------------------------------------------------
// ClustGeoNodeEncoder: per-cluster geometric features.
//   out[c] = [center(3), B(9)=cov/lambda_max, v0(3)=signed dir * dirwt, count]
//
// Pipeline (all graph-capturable, no allocations):
//   k_accum : one streaming pass, smem-privatized 10-moment accumulation,
//             per-block partials to global (plain stores).
//   k_reduce: warp-per-cluster reduction of partials + center/cov + 3x3
//             eigensolve (double) -> center, v0_unit, w1, w2, cov; zero g_sc.
//   k_sc    : second streaming pass, accumulate sc = sum x0*||xc - x0 v0||.
//   k_final : per-cluster finalize -> d_out.
// ---------------------------------------------------------------------------

#define MAXC 4096
#define CST  11          // per-cluster floats in smem/partials (11: coprime w/ 32 banks)
#define MAXB 192         // max blocks for k_accum

__device__ float  g_part[(size_t)MAXB * MAXC * CST];  // ~34.6 MB scratch
__device__ float4 g_cvec[MAXC * 2];                   // [c*2]={cx,cy,cz,cnt} [c*2+1]={vx,vy,vz,0}
__device__ float  g_cov [MAXC * 6];                   // a00,a11,a22,a01,a02,a12
__device__ float  g_w   [MAXC * 2];                   // w1 (mid), w2 (max)
__device__ float  g_sc  [MAXC];

// ---------------------------------------------------------------------------

__device__ __forceinline__ void accum_point(float* s, int id, float x, float y, float z)
{
    float* b = s + id * CST;
    atomicAdd(b + 0, 1.0f);
    atomicAdd(b + 1, x);
    atomicAdd(b + 2, y);
    atomicAdd(b + 3, z);
    atomicAdd(b + 4, x * x);
    atomicAdd(b + 5, y * y);
    atomicAdd(b + 6, z * z);
    atomicAdd(b + 7, x * y);
    atomicAdd(b + 8, x * z);
    atomicAdd(b + 9, y * z);
}

__global__ __launch_bounds__(1024, 1)
void k_accum(const float* __restrict__ data, const int* __restrict__ ids, int n, int nc)
{
    extern __shared__ float s[];
    const int tot = nc * CST;
    for (int j = threadIdx.x; j < tot; j += blockDim.x) s[j] = 0.0f;
    __syncthreads();

    const int gid    = blockIdx.x * blockDim.x + threadIdx.x;
    const int stride = gridDim.x * blockDim.x;
    const int nv4    = n >> 2;
    const float4* __restrict__ d4 = (const float4*)data;
    const int4*   __restrict__ i4 = (const int4*)ids;

    for (int g = gid; g < nv4; g += stride) {
        // 4 rows of 5 floats == 5 aligned float4 loads
        float4 q0 = d4[g * 5 + 0];
        float4 q1 = d4[g * 5 + 1];
        float4 q2 = d4[g * 5 + 2];
        float4 q3 = d4[g * 5 + 3];
        float4 q4 = d4[g * 5 + 4];
        int4   ii = i4[g];
        accum_point(s, ii.x, q0.x, q0.y, q0.z);
        accum_point(s, ii.y, q1.y, q1.z, q1.w);
        accum_point(s, ii.z, q2.z, q2.w, q3.x);
        accum_point(s, ii.w, q3.w, q4.x, q4.y);
    }
    // remainder rows (n not multiple of 4)
    for (int i = (nv4 << 2) + gid; i < n; i += stride) {
        float x = data[i * 5 + 0];
        float y = data[i * 5 + 1];
        float z = data[i * 5 + 2];
        accum_point(s, ids[i], x, y, z);
    }

    __syncthreads();
    float* dst = g_part + (size_t)blockIdx.x * MAXC * CST;
    for (int j = threadIdx.x; j < tot; j += blockDim.x) dst[j] = s[j];
}

// ---------------------------------------------------------------------------
// 3x3 symmetric eigensolve (double): returns mid/max eigenvalues and the
// eigenvector of the max eigenvalue (unnormalized sign — caller fixes sign
// via sc, exactly as the reference does).
// ---------------------------------------------------------------------------
__device__ void eig3_top(double a00, double a01, double a02,
                         double a11, double a12, double a22,
                         double& w1, double& w2,
                         double& vx, double& vy, double& vz)
{
    double q  = (a00 + a11 + a22) * (1.0 / 3.0);
    double p1 = a01 * a01 + a02 * a02 + a12 * a12;
    double b00 = a00 - q, b11 = a11 - q, b22 = a22 - q;
    double p2 = b00 * b00 + b11 * b11 + b22 * b22 + 2.0 * p1;
    if (p2 <= 1e-30) {           // (near-)scalar matrix: all eigenvalues == q
        w1 = q; w2 = q; vx = 0.0; vy = 0.0; vz = 1.0;
        return;
    }
    double p   = sqrt(p2 * (1.0 / 6.0));
    double inv = 1.0 / p;
    double c00 = b00 * inv, c11 = b11 * inv, c22 = b22 * inv;
    double c01 = a01 * inv, c02 = a02 * inv, c12 = a12 * inv;
    double detB = c00 * (c11 * c22 - c12 * c12)
                - c01 * (c01 * c22 - c12 * c02)
                + c02 * (c01 * c12 - c11 * c02);
    double r = 0.5 * detB;
    r = fmin(1.0, fmax(-1.0, r));
    double phi = acos(r) * (1.0 / 3.0);
    double e2 = q + 2.0 * p * cos(phi);                        // largest
    double e0 = q + 2.0 * p * cos(phi + 2.0943951023931953);   // smallest
    double e1 = 3.0 * q - e0 - e2;                             // middle
    w1 = e1; w2 = e2;

    // eigenvector for e2: cross products of rows of (A - e2*I)
    double r0x = a00 - e2, r0y = a01,      r0z = a02;
    double r1x = a01,      r1y = a11 - e2, r1z = a12;
    double r2x = a02,      r2y = a12,      r2z = a22 - e2;

    double u0x = r0y * r1z - r0z * r1y, u0y = r0z * r1x - r0x * r1z, u0z = r0x * r1y - r0y * r1x;
    double u1x = r0y * r2z - r0z * r2y, u1y = r0z * r2x - r0x * r2z, u1z = r0x * r2y - r0y * r2x;
    double u2x = r1y * r2z - r1z * r2y, u2y = r1z * r2x - r1x * r2z, u2z = r1x * r2y - r1y * r2x;

    double n0 = u0x * u0x + u0y * u0y + u0z * u0z;
    double n1 = u1x * u1x + u1y * u1y + u1z * u1z;
    double n2 = u2x * u2x + u2y * u2y + u2z * u2z;

    double bx = u0x, by = u0y, bz = u0z, bn = n0;
    if (n1 > bn) { bx = u1x; by = u1y; bz = u1z; bn = n1; }
    if (n2 > bn) { bx = u2x; by = u2y; bz = u2z; bn = n2; }

    if (bn < 1e-200) { vx = 0.0; vy = 0.0; vz = 1.0; return; }  // degenerate: dirwt ~ 0 anyway
    double s = rsqrt(bn);
    vx = bx * s; vy = by * s; vz = bz * s;
}

__global__ void k_reduce(int nc, int nb)
{
    int w    = (blockIdx.x * blockDim.x + threadIdx.x) >> 5;
    int lane = threadIdx.x & 31;
    if (w >= nc) return;

    float a[10];
#pragma unroll
    for (int k = 0; k < 10; k++) a[k] = 0.0f;

    for (int b = lane; b < nb; b += 32) {
        const float* p = g_part + (size_t)b * MAXC * CST + w * CST;
#pragma unroll
        for (int k = 0; k < 10; k++) a[k] += p[k];
    }
#pragma unroll
    for (int off = 16; off; off >>= 1) {
#pragma unroll
        for (int k = 0; k < 10; k++) a[k] += __shfl_down_sync(0xffffffffu, a[k], off);
    }
    if (lane != 0) return;

    double cnt  = (double)a[0];
    double safe = cnt > 1.0 ? cnt : 1.0;
    double cx = a[1] / safe, cy = a[2] / safe, cz = a[3] / safe;
    // cov = sum(x x^T) - cnt * c c^T
    double a00 = (double)a[4] - cnt * cx * cx;
    double a11 = (double)a[5] - cnt * cy * cy;
    double a22 = (double)a[6] - cnt * cz * cz;
    double a01 = (double)a[7] - cnt * cx * cy;
    double a02 = (double)a[8] - cnt * cx * cz;
    double a12 = (double)a[9] - cnt * cy * cz;

    double w1, w2, vx, vy, vz;
    eig3_top(a00, a01, a02, a11, a12, a22, w1, w2, vx, vy, vz);

    g_cvec[w * 2 + 0] = make_float4((float)cx, (float)cy, (float)cz, (float)cnt);
    g_cvec[w * 2 + 1] = make_float4((float)vx, (float)vy, (float)vz, 0.0f);
    g_cov[w * 6 + 0] = (float)a00;
    g_cov[w * 6 + 1] = (float)a11;
    g_cov[w * 6 + 2] = (float)a22;
    g_cov[w * 6 + 3] = (float)a01;
    g_cov[w * 6 + 4] = (float)a02;
    g_cov[w * 6 + 5] = (float)a12;
    g_w[w * 2 + 0] = (float)w1;
    g_w[w * 2 + 1] = (float)w2;
    g_sc[w] = 0.0f;   // zero before k_sc each replay
}

// ---------------------------------------------------------------------------

__device__ __forceinline__ void sc_point(float* s, int id, float x, float y, float z)
{
    float4 c  = g_cvec[id * 2 + 0];
    float4 v  = g_cvec[id * 2 + 1];
    float xcx = x - c.x, xcy = y - c.y, xcz = z - c.z;
    float x0  = xcx * v.x + xcy * v.y + xcz * v.z;
    float nn  = xcx * xcx + xcy * xcy + xcz * xcz - x0 * x0;
    float np0 = sqrtf(fmaxf(nn, 0.0f));
    atomicAdd(s + id, x0 * np0);
}

__global__ __launch_bounds__(1024, 1)
void k_sc(const float* __restrict__ data, const int* __restrict__ ids, int n, int nc)
{
    extern __shared__ float s[];
    for (int j = threadIdx.x; j < nc; j += blockDim.x) s[j] = 0.0f;
    __syncthreads();

    const int gid    = blockIdx.x * blockDim.x + threadIdx.x;
    const int stride = gridDim.x * blockDim.x;
    const int nv4    = n >> 2;
    const float4* __restrict__ d4 = (const float4*)data;
    const int4*   __restrict__ i4 = (const int4*)ids;

    for (int g = gid; g < nv4; g += stride) {
        float4 q0 = d4[g * 5 + 0];
        float4 q1 = d4[g * 5 + 1];
        float4 q2 = d4[g * 5 + 2];
        float4 q3 = d4[g * 5 + 3];
        float4 q4 = d4[g * 5 + 4];
        int4   ii = i4[g];
        sc_point(s, ii.x, q0.x, q0.y, q0.z);
        sc_point(s, ii.y, q1.y, q1.z, q1.w);
        sc_point(s, ii.z, q2.z, q2.w, q3.x);
        sc_point(s, ii.w, q3.w, q4.x, q4.y);
    }
    for (int i = (nv4 << 2) + gid; i < n; i += stride) {
        sc_point(s, ids[i], data[i * 5 + 0], data[i * 5 + 1], data[i * 5 + 2]);
    }

    __syncthreads();
    for (int j = threadIdx.x; j < nc; j += blockDim.x) {
        float v = s[j];
        if (v != 0.0f) atomicAdd(&g_sc[j], v);
    }
}

// ---------------------------------------------------------------------------

__global__ void k_final(float* __restrict__ out, int nc)
{
    int c = blockIdx.x * blockDim.x + threadIdx.x;
    if (c >= nc) return;

    float4 cc = g_cvec[c * 2 + 0];
    float4 vv = g_cvec[c * 2 + 1];
    float  cnt = cc.w;
    float  w1 = g_w[c * 2 + 0];
    float  w2 = g_w[c * 2 + 1];
    float  sc = g_sc[c];

    bool  small = cnt < 2.0f;
    float dirwt = (w2 == 0.0f) ? 0.0f : (1.0f - w1 / w2);
    float denom = (w2 == 0.0f) ? 1.0f : w2;
    float bs    = small ? 0.0f : (1.0f / denom);        // B = cov / lambda_max (DELTA=0)
    float vscl  = small ? 0.0f : ((sc < 0.0f) ? -dirwt : dirwt);

    float a00 = g_cov[c * 6 + 0] * bs;
    float a11 = g_cov[c * 6 + 1] * bs;
    float a22 = g_cov[c * 6 + 2] * bs;
    float a01 = g_cov[c * 6 + 3] * bs;
    float a02 = g_cov[c * 6 + 4] * bs;
    float a12 = g_cov[c * 6 + 5] * bs;

    float* o = out + (size_t)c * 16;
    o[0]  = cc.x; o[1]  = cc.y; o[2]  = cc.z;
    o[3]  = a00;  o[4]  = a01;  o[5]  = a02;
    o[6]  = a01;  o[7]  = a11;  o[8]  = a12;
    o[9]  = a02;  o[10] = a12;  o[11] = a22;
    o[12] = vv.x * vscl; o[13] = vv.y * vscl; o[14] = vv.z * vscl;
    o[15] = cnt;
}

// ---------------------------------------------------------------------------

extern "C" void kernel_launch(void* const* d_in, const int* in_sizes, int n_in,
                              void* d_out, int out_size)
{
    const float* data = (const float*)d_in[0];
    const int*   ids  = (const int*)d_in[1];
    const int    n    = in_sizes[1];
    int nc = out_size / 16;
    if (nc > MAXC) nc = MAXC;
    float* out = (float*)d_out;

    int sm = 148;
    cudaDeviceGetAttribute(&sm, cudaDevAttrMultiProcessorCount, 0);
    int nb = sm;
    if (nb > MAXB) nb = MAXB;
    if (nb < 1)    nb = 1;

    const size_t smem1 = (size_t)nc * CST * sizeof(float);   // 180,224 B @ nc=4096
    cudaFuncSetAttribute(k_accum, cudaFuncAttributeMaxDynamicSharedMemorySize, (int)smem1);

    k_accum<<<nb, 1024, smem1>>>(data, ids, n, nc);
    k_reduce<<<(nc * 32 + 255) / 256, 256>>>(nc, nb);
    k_sc<<<nb, 1024, (size_t)nc * sizeof(float)>>>(data, ids, n, nc);
    k_final<<<(nc + 255) / 256, 256>>>(out, nc);
}